// round 5
// baseline (speedup 1.0000x reference)
#include <cuda_runtime.h>
#include <cuda_bf16.h>
#include <stdint.h>

// Problem constants
#define NPIX  4096
#define CCH   256
#define DQK   32
#define BATCH 8
#define BQ    64
#define BK    64
#define NKT   (NPIX/BK)   // 64

// Scratch (static device arrays: allocation-guard safe)
__device__ __align__(256) float         g_q[BATCH * NPIX * DQK];  // [b][n][32]
__device__ __align__(256) float         g_k[BATCH * NPIX * DQK];  // [b][n][32]
__device__ __align__(256) __nv_bfloat16 g_v[BATCH * CCH * NPIX];  // [b][c][n]

// ---------------------------------------------------------------------------
// PTX helpers (sm_80+ only: mma.sync, ldmatrix, cp.async)
// ---------------------------------------------------------------------------
__device__ __forceinline__ uint32_t smem_u32(const void* p) {
    uint32_t a;
    asm("{ .reg .u64 t; cvta.to.shared.u64 t, %1; cvt.u32.u64 %0, t; }" : "=r"(a) : "l"(p));
    return a;
}
__device__ __forceinline__ void cp_async16(uint32_t dst, const void* src) {
    asm volatile("cp.async.cg.shared.global [%0], [%1], 16;\n" :: "r"(dst), "l"(src));
}
__device__ __forceinline__ void cp_commit() { asm volatile("cp.async.commit_group;\n" ::: "memory"); }
__device__ __forceinline__ void cp_wait0()  { asm volatile("cp.async.wait_group 0;\n" ::: "memory"); }

__device__ __forceinline__ void ldsm_x4(uint32_t& r0, uint32_t& r1, uint32_t& r2, uint32_t& r3,
                                        uint32_t addr) {
    asm volatile("ldmatrix.sync.aligned.m8n8.x4.shared.b16 {%0,%1,%2,%3}, [%4];\n"
                 : "=r"(r0), "=r"(r1), "=r"(r2), "=r"(r3) : "r"(addr));
}
__device__ __forceinline__ void mma_tf32(float* d, const uint32_t* a, uint32_t b0, uint32_t b1) {
    asm volatile(
        "mma.sync.aligned.m16n8k8.row.col.f32.tf32.tf32.f32 "
        "{%0,%1,%2,%3}, {%4,%5,%6,%7}, {%8,%9}, {%0,%1,%2,%3};\n"
        : "+f"(d[0]), "+f"(d[1]), "+f"(d[2]), "+f"(d[3])
        : "r"(a[0]), "r"(a[1]), "r"(a[2]), "r"(a[3]), "r"(b0), "r"(b1));
}
__device__ __forceinline__ void mma_bf16(float* d, const uint32_t* a, uint32_t b0, uint32_t b1) {
    asm volatile(
        "mma.sync.aligned.m16n8k16.row.col.f32.bf16.bf16.f32 "
        "{%0,%1,%2,%3}, {%4,%5,%6,%7}, {%8,%9}, {%0,%1,%2,%3};\n"
        : "+f"(d[0]), "+f"(d[1]), "+f"(d[2]), "+f"(d[3])
        : "r"(a[0]), "r"(a[1]), "r"(a[2]), "r"(a[3]), "r"(b0), "r"(b1));
}
__device__ __forceinline__ uint32_t pack_bf16(float lo, float hi) {
    uint32_t d;
    asm("cvt.rn.bf16x2.f32 %0, %1, %2;" : "=r"(d) : "f"(hi), "f"(lo));  // word = {hi,lo}
    return d;
}

// ---------------------------------------------------------------------------
// Kernel 1: tf32 tensor-core QKV projection (unchanged from round 4).
// ---------------------------------------------------------------------------
#define PJ_WS_BUF 17408
#define PJ_XS_OFF 34816
#define PJ_XS_BUF 33792
#define PJ_SMEM   102400

__global__ __launch_bounds__(256, 2) void proj_kernel(
    const float* __restrict__ x,
    const float* __restrict__ Wq, const float* __restrict__ bq,
    const float* __restrict__ Wk, const float* __restrict__ bk,
    const float* __restrict__ Wv, const float* __restrict__ bv)
{
    extern __shared__ char smc[];
    const uint32_t smb = smem_u32(smc);

    const int b   = blockIdx.z;
    const int r0  = blockIdx.y * 64;
    const int n0  = blockIdx.x * 128;
    const int tid = threadIdx.x;
    const int w   = tid >> 5;
    const int lane = tid & 31;
    const int g    = lane >> 2;
    const int tig  = lane & 3;
    const int wr = w >> 2, wn = w & 3;

    const float* xb = x + (size_t)b * CCH * NPIX;

    auto issue_chunk = [&](int kc) {
        const int c0 = kc * 64;
        const uint32_t wbuf = smb + PJ_WS_BUF * (kc & 1);
        const uint32_t xbuf = smb + PJ_XS_OFF + PJ_XS_BUF * (kc & 1);
#pragma unroll
        for (int i = 0; i < 4; i++) {
            int idx = tid + i * 256;
            int rr = idx >> 4, u = idx & 15;
            int r = r0 + rr;
            const float* src;
            if (r < 32)       src = Wq + (size_t)r * CCH;
            else if (r < 64)  src = Wk + (size_t)(r - 32) * CCH;
            else              src = Wv + (size_t)(r - 64) * CCH;
            cp_async16(wbuf + rr * 272 + u * 16, src + c0 + u * 4);
        }
#pragma unroll
        for (int i = 0; i < 8; i++) {
            int idx = tid + i * 256;
            int cc = idx >> 5, u = idx & 31;
            cp_async16(xbuf + cc * 528 + u * 16, xb + (size_t)(c0 + cc) * NPIX + n0 + u * 4);
        }
        cp_commit();
    };

    issue_chunk(0);

    float acc[2][4][4];
#pragma unroll
    for (int mf = 0; mf < 2; mf++)
#pragma unroll
        for (int nf = 0; nf < 4; nf++)
#pragma unroll
            for (int i = 0; i < 4; i++) acc[mf][nf][i] = 0.f;

    for (int kc = 0; kc < 4; kc++) {
        cp_wait0();
        __syncthreads();
        if (kc + 1 < 4) issue_chunk(kc + 1);

        const float* ws = (const float*)(smc + PJ_WS_BUF * (kc & 1));
        const float* xs = (const float*)(smc + PJ_XS_OFF + PJ_XS_BUF * (kc & 1));
#pragma unroll
        for (int kd = 0; kd < 8; kd++) {
            uint32_t a[2][4];
#pragma unroll
            for (int mf = 0; mf < 2; mf++) {
                int rb = wr * 32 + mf * 16;
                a[mf][0] = __float_as_uint(ws[(rb + g)     * 68 + kd * 8 + tig]);
                a[mf][1] = __float_as_uint(ws[(rb + g + 8) * 68 + kd * 8 + tig]);
                a[mf][2] = __float_as_uint(ws[(rb + g)     * 68 + kd * 8 + tig + 4]);
                a[mf][3] = __float_as_uint(ws[(rb + g + 8) * 68 + kd * 8 + tig + 4]);
            }
#pragma unroll
            for (int nf = 0; nf < 4; nf++) {
                int nb = wn * 32 + nf * 8 + g;
                uint32_t b0 = __float_as_uint(xs[(kd * 8 + tig)     * 132 + nb]);
                uint32_t b1 = __float_as_uint(xs[(kd * 8 + tig + 4) * 132 + nb]);
                mma_tf32(acc[0][nf], a[0], b0, b1);
                mma_tf32(acc[1][nf], a[1], b0, b1);
            }
        }
        __syncthreads();
    }

#pragma unroll
    for (int mf = 0; mf < 2; mf++) {
#pragma unroll
        for (int half = 0; half < 2; half++) {
            const int r = r0 + wr * 32 + mf * 16 + g + half * 8;
            const float* src_b = (r < 32) ? (bq + r) : (r < 64) ? (bk + r - 32) : (bv + r - 64);
            float bias = *src_b;
#pragma unroll
            for (int nf = 0; nf < 4; nf++) {
                const int n = n0 + wn * 32 + nf * 8 + 2 * tig;
                float v0 = acc[mf][nf][half * 2]     + bias;
                float v1 = acc[mf][nf][half * 2 + 1] + bias;
                if (r < 32) {
                    g_q[((size_t)b * NPIX + n)     * DQK + r] = v0;
                    g_q[((size_t)b * NPIX + n + 1) * DQK + r] = v1;
                } else if (r < 64) {
                    g_k[((size_t)b * NPIX + n)     * DQK + (r - 32)] = v0;
                    g_k[((size_t)b * NPIX + n + 1) * DQK + (r - 32)] = v1;
                } else {
                    uint32_t* dst = (uint32_t*)(g_v + (size_t)(b * CCH + (r - 64)) * NPIX + n);
                    *dst = pack_bf16(v0, v1);
                }
            }
        }
    }
}

// ---------------------------------------------------------------------------
// Kernel 2: HMMA flash attention, BQ=64, 256 threads, 2 CTAs/SM.
// Per kt: [wait L(kt); sync] issue L(kt+1); A(kt)->Pb; sync; C(kt).
// SMEM: V 2x[256][72]bf16 (73728) | K 2x[64][36]fp32 (18432)
//       | Pb [64][72]bf16 (9216, Q staging overlays) | Ls (512) = 101888 B
// ---------------------------------------------------------------------------
#define VB_OFF 0
#define VB_BUF 36864
#define KB_OFF 73728
#define KB_BUF 9216
#define PB_OFF 92160
#define LS_OFF 101376
#define ATT_SMEM 101888

__global__ __launch_bounds__(256, 2) void attn_kernel(
    const float* __restrict__ x,
    const float* __restrict__ gamma,
    float* __restrict__ out)
{
    extern __shared__ char smc[];
    const uint32_t smb = smem_u32(smc);

    const int tid  = threadIdx.x;
    const int w    = tid >> 5;
    const int lane = tid & 31;
    const int g    = lane >> 2;
    const int tig  = lane & 3;
    const int b    = blockIdx.y;
    const int n0   = blockIdx.x * BQ;

    const float*         qb = g_q + (size_t)b * NPIX * DQK;
    const float*         kb = g_k + (size_t)b * NPIX * DQK;
    const __nv_bfloat16* vb = g_v + (size_t)b * CCH * NPIX;

    // ---- prologue: L(0) = Q (into Pb region) + K0 + V0 ----
    {
#pragma unroll
        for (int i = 0; i < 2; i++) {                  // Q: 512 chunks
            int idx = tid + i * 256;
            int row = idx >> 3, u = idx & 7;
            cp_async16(smb + PB_OFF + row * 144 + u * 16,
                       qb + (size_t)(n0 + row) * DQK + u * 4);
        }
#pragma unroll
        for (int i = 0; i < 2; i++) {                  // K0: 512 chunks
            int idx = tid + i * 256;
            int row = idx >> 3, u = idx & 7;
            cp_async16(smb + KB_OFF + row * 144 + u * 16, kb + (size_t)row * DQK + u * 4);
        }
#pragma unroll
        for (int i = 0; i < 8; i++) {                  // V0: 2048 chunks
            int idx = tid + i * 256;
            int row = idx >> 3, u = idx & 7;
            cp_async16(smb + VB_OFF + row * 144 + u * 16, vb + (size_t)row * NPIX + u * 8);
        }
        cp_commit();
        cp_wait0();
        __syncthreads();
    }

    // ---- preload Q tf32 A-fragments (stage A role: qa = w>>1, mg = w&1) ----
    const int qa = w >> 1, mg = w & 1;
    uint32_t qf[4][4];
    {
        const float* qs = (const float*)(smc + PB_OFF);
        const int r0 = qa * 16 + g, r1 = r0 + 8;
#pragma unroll
        for (int kd = 0; kd < 4; kd++) {
            qf[kd][0] = __float_as_uint(qs[r0 * 36 + kd * 8 + tig]);
            qf[kd][1] = __float_as_uint(qs[r1 * 36 + kd * 8 + tig]);
            qf[kd][2] = __float_as_uint(qs[r0 * 36 + kd * 8 + tig + 4]);
            qf[kd][3] = __float_as_uint(qs[r1 * 36 + kd * 8 + tig + 4]);
        }
    }
    __syncthreads();   // all Q reads done before A(0) overwrites Pb region

    // stage C role: qc = w>>2 (q 32-group), cg = w&3 (c 64-group)
    const int qc = w >> 2, cg = w & 3;
    const uint32_t aRowOff = (uint32_t)(qc * 32 + (lane & 15)) * 144
                           + (uint32_t)((lane >> 4) * 8) * 2;
    const uint32_t bRow = (uint32_t)(cg * 64 + (lane & 7) + ((lane >> 4) << 3));
    const uint32_t bSeg = (uint32_t)(((lane >> 3) & 1) * 8) * 2;

    float acc[2][8][4];
#pragma unroll
    for (int mt = 0; mt < 2; mt++)
#pragma unroll
        for (int nt = 0; nt < 8; nt++)
#pragma unroll
            for (int i = 0; i < 4; i++) acc[mt][nt][i] = 0.f;

    float lp0 = 0.f, lp1 = 0.f;

    for (int kt = 0; kt < NKT; kt++) {
        if (kt) { cp_wait0(); __syncthreads(); }

        // ---- issue L(kt+1) into buffer (kt+1)&1 (its reader C(kt-1) finished
        //      before the sync above) ----
        if (kt + 1 < NKT) {
            const int m0 = (kt + 1) * BK;
            const uint32_t kbuf = smb + KB_OFF + KB_BUF * ((kt + 1) & 1);
            const uint32_t vbuf = smb + VB_OFF + VB_BUF * ((kt + 1) & 1);
#pragma unroll
            for (int i = 0; i < 2; i++) {
                int idx = tid + i * 256;
                int row = idx >> 3, u = idx & 7;
                cp_async16(kbuf + row * 144 + u * 16, kb + (size_t)(m0 + row) * DQK + u * 4);
            }
#pragma unroll
            for (int i = 0; i < 8; i++) {
                int idx = tid + i * 256;
                int row = idx >> 3, u = idx & 7;
                cp_async16(vbuf + row * 144 + u * 16, vb + (size_t)row * NPIX + m0 + u * 8);
            }
            cp_commit();
        }

        // ================= stage A(kt): S = Q K^T (tf32) -> exp -> Pb ========
        {
            const float* ks = (const float*)(smc + KB_OFF + KB_BUF * (kt & 1));
            uint32_t* pbW = (uint32_t*)(smc + PB_OFF);
            float s[4][4];
#pragma unroll
            for (int nt = 0; nt < 4; nt++) {
#pragma unroll
                for (int i = 0; i < 4; i++) s[nt][i] = 0.f;
                const int rowk = mg * 32 + nt * 8 + g;
#pragma unroll
                for (int kd = 0; kd < 4; kd++) {
                    uint32_t b0 = __float_as_uint(ks[rowk * 36 + kd * 8 + tig]);
                    uint32_t b1 = __float_as_uint(ks[rowk * 36 + kd * 8 + tig + 4]);
                    mma_tf32(s[nt], qf[kd], b0, b1);
                }
            }
            const int r0 = qa * 16 + g, r1 = r0 + 8;
            const int cbase = mg * 16 + tig;
#pragma unroll
            for (int nt = 0; nt < 4; nt++) {
                float p0 = __expf(s[nt][0]);
                float p1 = __expf(s[nt][1]);
                float p2 = __expf(s[nt][2]);
                float p3 = __expf(s[nt][3]);
                lp0 += p0 + p1;
                lp1 += p2 + p3;
                pbW[r0 * 36 + cbase + nt * 4] = pack_bf16(p0, p1);
                pbW[r1 * 36 + cbase + nt * 4] = pack_bf16(p2, p3);
            }
        }
        __syncthreads();   // Pb(kt) visible

        // ================= stage C(kt): O += P V^T (bf16) =================
        {
            const uint32_t aBase = smb + PB_OFF + aRowOff;
            const uint32_t vbase = smb + VB_OFF + VB_BUF * (kt & 1) + bRow * 144 + bSeg;
#pragma unroll
            for (int kk = 0; kk < 4; kk++) {
                uint32_t a0[4], a1[4];
                ldsm_x4(a0[0], a0[1], a0[2], a0[3], aBase + kk * 32);
                ldsm_x4(a1[0], a1[1], a1[2], a1[3], aBase + 2304 + kk * 32);
#pragma unroll
                for (int np = 0; np < 4; np++) {
                    uint32_t b0, b1, b2, b3;
                    ldsm_x4(b0, b1, b2, b3, vbase + np * 2304 + kk * 32);
                    mma_bf16(acc[0][2 * np],     a0, b0, b1);
                    mma_bf16(acc[0][2 * np + 1], a0, b2, b3);
                    mma_bf16(acc[1][2 * np],     a1, b0, b1);
                    mma_bf16(acc[1][2 * np + 1], a1, b2, b3);
                }
            }
        }
    }

    // ---- lsum reduction ----
    lp0 += __shfl_xor_sync(0xffffffffu, lp0, 1);
    lp0 += __shfl_xor_sync(0xffffffffu, lp0, 2);
    lp1 += __shfl_xor_sync(0xffffffffu, lp1, 1);
    lp1 += __shfl_xor_sync(0xffffffffu, lp1, 2);
    float* Ls2 = (float*)(smc + LS_OFF);
    if (tig == 0) {
        Ls2[mg * 64 + qa * 16 + g]     = lp0;
        Ls2[mg * 64 + qa * 16 + g + 8] = lp1;
    }
    __syncthreads();

    // ---- epilogue: out = gamma * O / l + x ----
    const float gm = gamma[0];
    const float* xb = x + (size_t)b * CCH * NPIX;
    float* ob = out + (size_t)b * CCH * NPIX;
#pragma unroll
    for (int mt = 0; mt < 2; mt++) {
        const int r0 = qc * 32 + mt * 16 + g;
        const float sc0 = gm / (Ls2[r0] + Ls2[64 + r0]);
        const float sc1 = gm / (Ls2[r0 + 8] + Ls2[64 + r0 + 8]);
#pragma unroll
        for (int nt = 0; nt < 8; nt++) {
            const int c = cg * 64 + nt * 8 + 2 * tig;
            size_t o00 = (size_t)c * NPIX + n0 + r0;
            size_t o01 = o00 + NPIX;
            ob[o00]     = acc[mt][nt][0] * sc0 + xb[o00];
            ob[o01]     = acc[mt][nt][1] * sc0 + xb[o01];
            ob[o00 + 8] = acc[mt][nt][2] * sc1 + xb[o00 + 8];
            ob[o01 + 8] = acc[mt][nt][3] * sc1 + xb[o01 + 8];
        }
    }
}

// ---------------------------------------------------------------------------
// Launch
// ---------------------------------------------------------------------------
extern "C" void kernel_launch(void* const* d_in, const int* in_sizes, int n_in,
                              void* d_out, int out_size)
{
    (void)in_sizes; (void)n_in; (void)out_size;
    const float* x     = (const float*)d_in[0];
    const float* Wq    = (const float*)d_in[1];
    const float* bq    = (const float*)d_in[2];
    const float* Wk    = (const float*)d_in[3];
    const float* bk    = (const float*)d_in[4];
    const float* Wv    = (const float*)d_in[5];
    const float* bv    = (const float*)d_in[6];
    const float* gamma = (const float*)d_in[7];
    float* out = (float*)d_out;

    cudaFuncSetAttribute(proj_kernel, cudaFuncAttributeMaxDynamicSharedMemorySize, PJ_SMEM);
    dim3 pgrid(NPIX / 128, 320 / 64, BATCH);
    proj_kernel<<<pgrid, 256, PJ_SMEM>>>(x, Wq, bq, Wk, bk, Wv, bv);

    cudaFuncSetAttribute(attn_kernel, cudaFuncAttributeMaxDynamicSharedMemorySize, ATT_SMEM);
    dim3 agrid(NPIX / BQ, BATCH);
    attn_kernel<<<agrid, 256, ATT_SMEM>>>(x, gamma, out);
}

// round 6
// speedup vs baseline: 1.0487x; 1.0487x over previous
#include <cuda_runtime.h>
#include <cuda_bf16.h>
#include <stdint.h>

// Problem constants
#define NPIX  4096
#define CCH   256
#define DQK   32
#define BATCH 8
#define BQ    128
#define BK    64
#define NKT   (NPIX/BK)   // 64

// Scratch (static device arrays: allocation-guard safe)
__device__ __align__(256) float         g_q[BATCH * NPIX * DQK];  // [b][n][32]
__device__ __align__(256) float         g_k[BATCH * NPIX * DQK];  // [b][n][32]
__device__ __align__(256) __nv_bfloat16 g_v[BATCH * CCH * NPIX];  // [b][c][n]

// ---------------------------------------------------------------------------
// PTX helpers (sm_80+ only: mma.sync, ldmatrix, cp.async)
// ---------------------------------------------------------------------------
__device__ __forceinline__ uint32_t smem_u32(const void* p) {
    uint32_t a;
    asm("{ .reg .u64 t; cvta.to.shared.u64 t, %1; cvt.u32.u64 %0, t; }" : "=r"(a) : "l"(p));
    return a;
}
__device__ __forceinline__ void cp_async16(uint32_t dst, const void* src) {
    asm volatile("cp.async.cg.shared.global [%0], [%1], 16;\n" :: "r"(dst), "l"(src));
}
__device__ __forceinline__ void cp_commit() { asm volatile("cp.async.commit_group;\n" ::: "memory"); }
__device__ __forceinline__ void cp_wait1()  { asm volatile("cp.async.wait_group 1;\n" ::: "memory"); }

__device__ __forceinline__ void ldsm_x4(uint32_t& r0, uint32_t& r1, uint32_t& r2, uint32_t& r3,
                                        uint32_t addr) {
    asm volatile("ldmatrix.sync.aligned.m8n8.x4.shared.b16 {%0,%1,%2,%3}, [%4];\n"
                 : "=r"(r0), "=r"(r1), "=r"(r2), "=r"(r3) : "r"(addr));
}
__device__ __forceinline__ void mma_tf32(float* d, const uint32_t* a, uint32_t b0, uint32_t b1) {
    asm volatile(
        "mma.sync.aligned.m16n8k8.row.col.f32.tf32.tf32.f32 "
        "{%0,%1,%2,%3}, {%4,%5,%6,%7}, {%8,%9}, {%0,%1,%2,%3};\n"
        : "+f"(d[0]), "+f"(d[1]), "+f"(d[2]), "+f"(d[3])
        : "r"(a[0]), "r"(a[1]), "r"(a[2]), "r"(a[3]), "r"(b0), "r"(b1));
}
__device__ __forceinline__ void mma_bf16(float* d, const uint32_t* a, uint32_t b0, uint32_t b1) {
    asm volatile(
        "mma.sync.aligned.m16n8k16.row.col.f32.bf16.bf16.f32 "
        "{%0,%1,%2,%3}, {%4,%5,%6,%7}, {%8,%9}, {%0,%1,%2,%3};\n"
        : "+f"(d[0]), "+f"(d[1]), "+f"(d[2]), "+f"(d[3])
        : "r"(a[0]), "r"(a[1]), "r"(a[2]), "r"(a[3]), "r"(b0), "r"(b1));
}
__device__ __forceinline__ uint32_t pack_bf16(float lo, float hi) {
    uint32_t d;
    asm("cvt.rn.bf16x2.f32 %0, %1, %2;" : "=r"(d) : "f"(hi), "f"(lo));  // word = {hi,lo}
    return d;
}

// ---------------------------------------------------------------------------
// Kernel 1: tf32 tensor-core QKV projection (unchanged — ~41 us).
// ---------------------------------------------------------------------------
#define PJ_WS_BUF 17408
#define PJ_XS_OFF 34816
#define PJ_XS_BUF 33792
#define PJ_SMEM   102400

__global__ __launch_bounds__(256, 2) void proj_kernel(
    const float* __restrict__ x,
    const float* __restrict__ Wq, const float* __restrict__ bq,
    const float* __restrict__ Wk, const float* __restrict__ bk,
    const float* __restrict__ Wv, const float* __restrict__ bv)
{
    extern __shared__ char smc[];
    const uint32_t smb = smem_u32(smc);

    const int b   = blockIdx.z;
    const int r0  = blockIdx.y * 64;
    const int n0  = blockIdx.x * 128;
    const int tid = threadIdx.x;
    const int w   = tid >> 5;
    const int lane = tid & 31;
    const int g    = lane >> 2;
    const int tig  = lane & 3;
    const int wr = w >> 2, wn = w & 3;

    const float* xb = x + (size_t)b * CCH * NPIX;

    auto issue_chunk = [&](int kc) {
        const int c0 = kc * 64;
        const uint32_t wbuf = smb + PJ_WS_BUF * (kc & 1);
        const uint32_t xbuf = smb + PJ_XS_OFF + PJ_XS_BUF * (kc & 1);
#pragma unroll
        for (int i = 0; i < 4; i++) {
            int idx = tid + i * 256;
            int rr = idx >> 4, u = idx & 15;
            int r = r0 + rr;
            const float* src;
            if (r < 32)       src = Wq + (size_t)r * CCH;
            else if (r < 64)  src = Wk + (size_t)(r - 32) * CCH;
            else              src = Wv + (size_t)(r - 64) * CCH;
            cp_async16(wbuf + rr * 272 + u * 16, src + c0 + u * 4);
        }
#pragma unroll
        for (int i = 0; i < 8; i++) {
            int idx = tid + i * 256;
            int cc = idx >> 5, u = idx & 31;
            cp_async16(xbuf + cc * 528 + u * 16, xb + (size_t)(c0 + cc) * NPIX + n0 + u * 4);
        }
        cp_commit();
    };

    issue_chunk(0);

    float acc[2][4][4];
#pragma unroll
    for (int mf = 0; mf < 2; mf++)
#pragma unroll
        for (int nf = 0; nf < 4; nf++)
#pragma unroll
            for (int i = 0; i < 4; i++) acc[mf][nf][i] = 0.f;

    for (int kc = 0; kc < 4; kc++) {
        asm volatile("cp.async.wait_group 0;\n" ::: "memory");
        __syncthreads();
        if (kc + 1 < 4) issue_chunk(kc + 1);

        const float* ws = (const float*)(smc + PJ_WS_BUF * (kc & 1));
        const float* xs = (const float*)(smc + PJ_XS_OFF + PJ_XS_BUF * (kc & 1));
#pragma unroll
        for (int kd = 0; kd < 8; kd++) {
            uint32_t a[2][4];
#pragma unroll
            for (int mf = 0; mf < 2; mf++) {
                int rb = wr * 32 + mf * 16;
                a[mf][0] = __float_as_uint(ws[(rb + g)     * 68 + kd * 8 + tig]);
                a[mf][1] = __float_as_uint(ws[(rb + g + 8) * 68 + kd * 8 + tig]);
                a[mf][2] = __float_as_uint(ws[(rb + g)     * 68 + kd * 8 + tig + 4]);
                a[mf][3] = __float_as_uint(ws[(rb + g + 8) * 68 + kd * 8 + tig + 4]);
            }
#pragma unroll
            for (int nf = 0; nf < 4; nf++) {
                int nb = wn * 32 + nf * 8 + g;
                uint32_t b0 = __float_as_uint(xs[(kd * 8 + tig)     * 132 + nb]);
                uint32_t b1 = __float_as_uint(xs[(kd * 8 + tig + 4) * 132 + nb]);
                mma_tf32(acc[0][nf], a[0], b0, b1);
                mma_tf32(acc[1][nf], a[1], b0, b1);
            }
        }
        __syncthreads();
    }

#pragma unroll
    for (int mf = 0; mf < 2; mf++) {
#pragma unroll
        for (int half = 0; half < 2; half++) {
            const int r = r0 + wr * 32 + mf * 16 + g + half * 8;
            const float* src_b = (r < 32) ? (bq + r) : (r < 64) ? (bk + r - 32) : (bv + r - 64);
            float bias = *src_b;
#pragma unroll
            for (int nf = 0; nf < 4; nf++) {
                const int n = n0 + wn * 32 + nf * 8 + 2 * tig;
                float v0 = acc[mf][nf][half * 2]     + bias;
                float v1 = acc[mf][nf][half * 2 + 1] + bias;
                if (r < 32) {
                    g_q[((size_t)b * NPIX + n)     * DQK + r] = v0;
                    g_q[((size_t)b * NPIX + n + 1) * DQK + r] = v1;
                } else if (r < 64) {
                    g_k[((size_t)b * NPIX + n)     * DQK + (r - 32)] = v0;
                    g_k[((size_t)b * NPIX + n + 1) * DQK + (r - 32)] = v1;
                } else {
                    uint32_t* dst = (uint32_t*)(g_v + (size_t)(b * CCH + (r - 64)) * NPIX + n);
                    *dst = pack_bf16(v0, v1);
                }
            }
        }
    }
}

// ---------------------------------------------------------------------------
// Kernel 2: HMMA flash attention — FAT WARPS. 256 threads, 1 CTA/SM, 255 regs.
// BQ=128. Per warp: stage A 16q x 64m (tf32), stage C 32q x 128c (bf16,
// 128 fp32 acc regs). Round-4 pipeline: one sync/kt, A(kt) then C(kt-1),
// K/V 4-buffered (prefetch distance 2, wait_group 1), Pb double-buffered.
// SMEM: V 4x[256][72]bf16 (147456) | K 4x[64][36]fp32 (36864)
//       | Pb 2x[128][72]bf16 (36864; Q staged in Pb[1]) | Ls 512  = 221696 B
// ---------------------------------------------------------------------------
#define VB_OFF 0
#define VB_BUF 36864
#define KB_OFF 147456
#define KB_BUF 9216
#define PB_OFF 184320
#define PB_BUF 18432
#define LS_OFF 221184
#define ATT_SMEM 221696

__global__ __launch_bounds__(256, 1) void attn_kernel(
    const float* __restrict__ x,
    const float* __restrict__ gamma,
    float* __restrict__ out)
{
    extern __shared__ char smc[];
    const uint32_t smb = smem_u32(smc);

    const int tid  = threadIdx.x;
    const int w    = tid >> 5;
    const int lane = tid & 31;
    const int g    = lane >> 2;
    const int tig  = lane & 3;
    const int b    = blockIdx.y;
    const int n0   = blockIdx.x * BQ;

    const float*         qb = g_q + (size_t)b * NPIX * DQK;
    const float*         kb = g_k + (size_t)b * NPIX * DQK;
    const __nv_bfloat16* vb = g_v + (size_t)b * CCH * NPIX;

    // ---- prologue: [Q + K0 + V0] commit, [K1 + V1] commit, wait1 ----
    {
#pragma unroll
        for (int i = 0; i < 4; i++) {                  // Q -> Pb[1]: 1024 chunks
            int idx = tid + i * 256;
            int row = idx >> 3, u = idx & 7;
            cp_async16(smb + PB_OFF + PB_BUF + row * 144 + u * 16,
                       qb + (size_t)(n0 + row) * DQK + u * 4);
        }
#pragma unroll
        for (int i = 0; i < 2; i++) {                  // K0: 512 chunks
            int idx = tid + i * 256;
            int row = idx >> 3, u = idx & 7;
            cp_async16(smb + KB_OFF + row * 144 + u * 16, kb + (size_t)row * DQK + u * 4);
        }
#pragma unroll
        for (int i = 0; i < 8; i++) {                  // V0: 2048 chunks
            int idx = tid + i * 256;
            int row = idx >> 3, u = idx & 7;
            cp_async16(smb + VB_OFF + row * 144 + u * 16, vb + (size_t)row * NPIX + u * 8);
        }
        cp_commit();
#pragma unroll
        for (int i = 0; i < 2; i++) {                  // K1
            int idx = tid + i * 256;
            int row = idx >> 3, u = idx & 7;
            cp_async16(smb + KB_OFF + KB_BUF + row * 144 + u * 16,
                       kb + (size_t)(BK + row) * DQK + u * 4);
        }
#pragma unroll
        for (int i = 0; i < 8; i++) {                  // V1
            int idx = tid + i * 256;
            int row = idx >> 3, u = idx & 7;
            cp_async16(smb + VB_OFF + VB_BUF + row * 144 + u * 16,
                       vb + (size_t)row * NPIX + BK + u * 8);
        }
        cp_commit();
        cp_wait1();
        __syncthreads();
    }

    // ---- preload Q tf32 A-fragments (stage A role: qa = w, 16 q rows) ----
    uint32_t qf[4][4];
    {
        const float* qs = (const float*)(smc + PB_OFF + PB_BUF);
        const int r0 = w * 16 + g, r1 = r0 + 8;
#pragma unroll
        for (int kd = 0; kd < 4; kd++) {
            qf[kd][0] = __float_as_uint(qs[r0 * 36 + kd * 8 + tig]);
            qf[kd][1] = __float_as_uint(qs[r1 * 36 + kd * 8 + tig]);
            qf[kd][2] = __float_as_uint(qs[r0 * 36 + kd * 8 + tig + 4]);
            qf[kd][3] = __float_as_uint(qs[r1 * 36 + kd * 8 + tig + 4]);
        }
    }
    __syncthreads();   // Q reads done before A(1) overwrites Pb[1]

    // stage C role: qg2 = w>>1 (32q group), ch = w&1 (128c half)
    const int qg2 = w >> 1, ch = w & 1;
    const uint32_t aRowOff = (uint32_t)(qg2 * 32 + (lane & 15)) * 144
                           + (uint32_t)((lane >> 4) * 8) * 2;
    const uint32_t vRowOff = (uint32_t)(ch * 128 + (lane & 7) + ((lane >> 4) << 3)) * 144
                           + (uint32_t)(((lane >> 3) & 1) * 8) * 2;

    float acc[2][16][4];
#pragma unroll
    for (int mt = 0; mt < 2; mt++)
#pragma unroll
        for (int nf = 0; nf < 16; nf++)
#pragma unroll
            for (int i = 0; i < 4; i++) acc[mt][nf][i] = 0.f;

    float lp0 = 0.f, lp1 = 0.f;

    for (int kt = 0; kt < NKT; kt++) {
        if (kt) { cp_wait1(); __syncthreads(); }

        // ---- issue L(kt+2) into buffer (kt+2)&3 ----
        if (kt + 2 < NKT) {
            const int m0 = (kt + 2) * BK;
            const uint32_t kbuf = smb + KB_OFF + KB_BUF * ((kt + 2) & 3);
            const uint32_t vbuf = smb + VB_OFF + VB_BUF * ((kt + 2) & 3);
#pragma unroll
            for (int i = 0; i < 2; i++) {
                int idx = tid + i * 256;
                int row = idx >> 3, u = idx & 7;
                cp_async16(kbuf + row * 144 + u * 16, kb + (size_t)(m0 + row) * DQK + u * 4);
            }
#pragma unroll
            for (int i = 0; i < 8; i++) {
                int idx = tid + i * 256;
                int row = idx >> 3, u = idx & 7;
                cp_async16(vbuf + row * 144 + u * 16, vb + (size_t)row * NPIX + m0 + u * 8);
            }
        }
        cp_commit();

        // ===== stage A(kt): S[16q x 64m] = Q K^T (tf32) -> exp -> Pb[kt&1] ===
        {
            const float* ks = (const float*)(smc + KB_OFF + KB_BUF * (kt & 3));
            uint32_t* pbW = (uint32_t*)(smc + PB_OFF + PB_BUF * (kt & 1));
            const int r0 = w * 16 + g, r1 = r0 + 8;
#pragma unroll
            for (int h = 0; h < 2; h++) {              // two nt-halves (reg diet)
                float s[4][4];
#pragma unroll
                for (int nt4 = 0; nt4 < 4; nt4++) {
#pragma unroll
                    for (int i = 0; i < 4; i++) s[nt4][i] = 0.f;
                    const int rowk = (h * 4 + nt4) * 8 + g;
#pragma unroll
                    for (int kd = 0; kd < 4; kd++) {
                        uint32_t b0 = __float_as_uint(ks[rowk * 36 + kd * 8 + tig]);
                        uint32_t b1 = __float_as_uint(ks[rowk * 36 + kd * 8 + tig + 4]);
                        mma_tf32(s[nt4], qf[kd], b0, b1);
                    }
                }
#pragma unroll
                for (int nt4 = 0; nt4 < 4; nt4++) {
                    const int nt = h * 4 + nt4;
                    float p0 = __expf(s[nt4][0]);
                    float p1 = __expf(s[nt4][1]);
                    float p2 = __expf(s[nt4][2]);
                    float p3 = __expf(s[nt4][3]);
                    lp0 += p0 + p1;
                    lp1 += p2 + p3;
                    pbW[r0 * 36 + nt * 4 + tig] = pack_bf16(p0, p1);
                    pbW[r1 * 36 + nt * 4 + tig] = pack_bf16(p2, p3);
                }
            }
        }

        // ===== stage C(kt-1): O[32q x 128c] += P V^T (bf16) =====
        if (kt) {
            const int j = kt - 1;
            const uint32_t aBase = smb + PB_OFF + PB_BUF * (j & 1) + aRowOff;
            const uint32_t vbase = smb + VB_OFF + VB_BUF * (j & 3) + vRowOff;
#pragma unroll
            for (int kk = 0; kk < 4; kk++) {
                uint32_t a0[4], a1[4];
                ldsm_x4(a0[0], a0[1], a0[2], a0[3], aBase + kk * 32);
                ldsm_x4(a1[0], a1[1], a1[2], a1[3], aBase + 2304 + kk * 32);
#pragma unroll
                for (int np = 0; np < 8; np++) {
                    uint32_t b0, b1, b2, b3;
                    ldsm_x4(b0, b1, b2, b3, vbase + np * 2304 + kk * 32);
                    mma_bf16(acc[0][2 * np],     a0, b0, b1);
                    mma_bf16(acc[0][2 * np + 1], a0, b2, b3);
                    mma_bf16(acc[1][2 * np],     a1, b0, b1);
                    mma_bf16(acc[1][2 * np + 1], a1, b2, b3);
                }
            }
        }
    }

    // tail: C(63)
    __syncthreads();
    {
        const int j = NKT - 1;
        const uint32_t aBase = smb + PB_OFF + PB_BUF * (j & 1) + aRowOff;
        const uint32_t vbase = smb + VB_OFF + VB_BUF * (j & 3) + vRowOff;
#pragma unroll
        for (int kk = 0; kk < 4; kk++) {
            uint32_t a0[4], a1[4];
            ldsm_x4(a0[0], a0[1], a0[2], a0[3], aBase + kk * 32);
            ldsm_x4(a1[0], a1[1], a1[2], a1[3], aBase + 2304 + kk * 32);
#pragma unroll
            for (int np = 0; np < 8; np++) {
                uint32_t b0, b1, b2, b3;
                ldsm_x4(b0, b1, b2, b3, vbase + np * 2304 + kk * 32);
                mma_bf16(acc[0][2 * np],     a0, b0, b1);
                mma_bf16(acc[0][2 * np + 1], a0, b2, b3);
                mma_bf16(acc[1][2 * np],     a1, b0, b1);
                mma_bf16(acc[1][2 * np + 1], a1, b2, b3);
            }
        }
    }

    // ---- lsum: quad-reduce (full m=64 per warp) then publish ----
    lp0 += __shfl_xor_sync(0xffffffffu, lp0, 1);
    lp0 += __shfl_xor_sync(0xffffffffu, lp0, 2);
    lp1 += __shfl_xor_sync(0xffffffffu, lp1, 1);
    lp1 += __shfl_xor_sync(0xffffffffu, lp1, 2);
    float* Ls = (float*)(smc + LS_OFF);
    if (tig == 0) {
        Ls[w * 16 + g]     = lp0;
        Ls[w * 16 + g + 8] = lp1;
    }
    __syncthreads();

    // ---- epilogue: out = gamma * O / l + x ----
    const float gm = gamma[0];
    const float* xb = x + (size_t)b * CCH * NPIX;
    float* ob = out + (size_t)b * CCH * NPIX;
#pragma unroll
    for (int mt = 0; mt < 2; mt++) {
        const int r0 = qg2 * 32 + mt * 16 + g;
        const float sc0 = gm / Ls[r0];
        const float sc1 = gm / Ls[r0 + 8];
#pragma unroll
        for (int nf = 0; nf < 16; nf++) {
            const int c = ch * 128 + nf * 8 + 2 * tig;
            size_t o00 = (size_t)c * NPIX + n0 + r0;
            size_t o01 = o00 + NPIX;
            ob[o00]     = acc[mt][nf][0] * sc0 + xb[o00];
            ob[o01]     = acc[mt][nf][1] * sc0 + xb[o01];
            ob[o00 + 8] = acc[mt][nf][2] * sc1 + xb[o00 + 8];
            ob[o01 + 8] = acc[mt][nf][3] * sc1 + xb[o01 + 8];
        }
    }
}

// ---------------------------------------------------------------------------
// Launch
// ---------------------------------------------------------------------------
extern "C" void kernel_launch(void* const* d_in, const int* in_sizes, int n_in,
                              void* d_out, int out_size)
{
    (void)in_sizes; (void)n_in; (void)out_size;
    const float* x     = (const float*)d_in[0];
    const float* Wq    = (const float*)d_in[1];
    const float* bq    = (const float*)d_in[2];
    const float* Wk    = (const float*)d_in[3];
    const float* bk    = (const float*)d_in[4];
    const float* Wv    = (const float*)d_in[5];
    const float* bv    = (const float*)d_in[6];
    const float* gamma = (const float*)d_in[7];
    float* out = (float*)d_out;

    cudaFuncSetAttribute(proj_kernel, cudaFuncAttributeMaxDynamicSharedMemorySize, PJ_SMEM);
    dim3 pgrid(NPIX / 128, 320 / 64, BATCH);
    proj_kernel<<<pgrid, 256, PJ_SMEM>>>(x, Wq, bq, Wk, bk, Wv, bv);

    cudaFuncSetAttribute(attn_kernel, cudaFuncAttributeMaxDynamicSharedMemorySize, ATT_SMEM);
    dim3 agrid(NPIX / BQ, BATCH);
    attn_kernel<<<agrid, 256, ATT_SMEM>>>(x, gamma, out);
}